// round 14
// baseline (speedup 1.0000x reference)
#include <cuda_runtime.h>
#include <cuda_bf16.h>
#include <math.h>
#include <stdint.h>

// ---------------------------------------------------------------------------
// Problem constants: N=50000, E=800000, IN=256, C=64, H=4
// ---------------------------------------------------------------------------
#define NMAX   50000
#define EMAX   800000
#define E2MAX  (EMAX + NMAX)
#define HC     256          // H*C
#define CCH    64           // C
#define NEG_SLOPE 0.2f
#define SCAN_BLK 64         // >= ceil(NMAX/1024) = 49

// ---------------------------------------------------------------------------
// Scratch
// ---------------------------------------------------------------------------
__device__ __align__(256) float g_xl[(size_t)NMAX * HC];
__device__ __align__(256) float g_xr[(size_t)NMAX * HC];
__device__ __align__(256) __nv_bfloat16 g_ah[(size_t)NMAX * HC];
__device__ __align__(256) __nv_bfloat16 g_al[(size_t)NMAX * HC];
__device__ __align__(256) __nv_bfloat16 g_wh[2][256 * 256 + 2 * 256 * 64];
__device__ __align__(256) __nv_bfloat16 g_wl[2][256 * 256 + 2 * 256 * 64];
__device__ __align__(256) int   g_cnt[NMAX];
__device__ __align__(256) float g_sumattr[NMAX];
__device__ __align__(256) int   g_off[NMAX + 2];
__device__ __align__(256) int   g_cursor[NMAX];
__device__ __align__(256) int   g_csr_src[E2MAX];
__device__ __align__(256) float g_csr_attr[E2MAX];
__device__ __align__(256) int   g_bsum[SCAN_BLK];
__device__ __align__(256) int   g_boff[SCAN_BLK];
__device__ int g_is64;

#define WOFF1 0
#define WOFF2 (256 * 256)
#define WOFF3 (256 * 256 + 256 * 64)

// ---------------------------------------------------------------------------
// edge_index dtype probe + CSR build
// ---------------------------------------------------------------------------
__device__ __forceinline__ int load_idx(const void* ei, int is64, size_t pos) {
    if (is64) return (int)((const long long*)ei)[pos];
    return ((const int*)ei)[pos];
}
__global__ void detect_kernel(const int* ei32, int e) {
    if (threadIdx.x != 0 || blockIdx.x != 0) return;
    int nz = 0;
    int lim = (e < 64) ? e : 64;
    for (int i = 0; i < lim; ++i) nz |= ei32[2 * i + 1];
    g_is64 = (nz == 0) ? 1 : 0;
}
__global__ void init_kernel(int n) {
    int i = blockIdx.x * blockDim.x + threadIdx.x;
    if (i < n) { g_cnt[i] = 0; g_sumattr[i] = 0.f; }
}
__global__ void count_kernel(const void* __restrict__ ei,
                             const float* __restrict__ eattr, int e, int n) {
    int i = blockIdx.x * blockDim.x + threadIdx.x;
    if (i >= e) return;
    int is64 = g_is64;
    int d = load_idx(ei, is64, (size_t)e + i);
    if ((unsigned)d >= (unsigned)n) return;
    atomicAdd(&g_cnt[d], 1);
    atomicAdd(&g_sumattr[d], eattr[i]);
}

// --- multi-block decoupled scan of (cnt[i]+1) ---
// pass 1: per-1024-block sums
__global__ void scan_pass1(int n) {
    __shared__ int wsum[32];
    int tid = threadIdx.x, lane = tid & 31, wid = tid >> 5;
    int i = blockIdx.x * 1024 + tid;
    int x = (i < n) ? (g_cnt[i] + 1) : 0;
    #pragma unroll
    for (int d = 16; d > 0; d >>= 1) x += __shfl_xor_sync(0xffffffffu, x, d);
    if (lane == 0) wsum[wid] = x;
    __syncthreads();
    if (wid == 0) {
        int s = wsum[lane];
        #pragma unroll
        for (int d = 16; d > 0; d >>= 1) s += __shfl_xor_sync(0xffffffffu, s, d);
        if (lane == 0) g_bsum[blockIdx.x] = s;
    }
}
// pass 2: exclusive scan of block sums (nb <= 64; 1 block, 64 threads)
__global__ void scan_pass2(int nb, int n) {
    __shared__ int ws[2];
    int tid = threadIdx.x, lane = tid & 31, wid = tid >> 5;
    int v = (tid < nb) ? g_bsum[tid] : 0;
    int x = v;
    #pragma unroll
    for (int d = 1; d < 32; d <<= 1) {
        int t = __shfl_up_sync(0xffffffffu, x, d);
        if (lane >= d) x += t;
    }
    if (lane == 31) ws[wid] = x;
    __syncthreads();
    int incl = x + ((wid == 1) ? ws[0] : 0);
    int excl = incl - v;
    if (tid < nb) g_boff[tid] = excl;
    if (tid == nb - 1) g_off[n] = incl;
}
// pass 3: per-block exclusive scan + block offset -> g_off/g_cursor
__global__ void scan_pass3(int n) {
    __shared__ int wsum[32];
    int tid = threadIdx.x, lane = tid & 31, wid = tid >> 5;
    int i = blockIdx.x * 1024 + tid;
    int v = (i < n) ? (g_cnt[i] + 1) : 0;
    int x = v;
    #pragma unroll
    for (int d = 1; d < 32; d <<= 1) {
        int t = __shfl_up_sync(0xffffffffu, x, d);
        if (lane >= d) x += t;
    }
    if (lane == 31) wsum[wid] = x;
    __syncthreads();
    if (wid == 0) {
        int s = wsum[lane];
        #pragma unroll
        for (int d = 1; d < 32; d <<= 1) {
            int t = __shfl_up_sync(0xffffffffu, s, d);
            if (lane >= d) s += t;
        }
        wsum[lane] = s;
    }
    __syncthreads();
    int woff = (wid > 0) ? wsum[wid - 1] : 0;
    int excl = x - v + woff + g_boff[blockIdx.x];
    if (i < n) { g_off[i] = excl; g_cursor[i] = excl; }
}

__global__ void fill_kernel(const void* __restrict__ ei,
                            const float* __restrict__ eattr, int e, int n) {
    int i = blockIdx.x * blockDim.x + threadIdx.x;
    if (i >= e) return;
    int is64 = g_is64;
    int s = load_idx(ei, is64, (size_t)i);
    int d = load_idx(ei, is64, (size_t)e + i);
    if ((unsigned)d >= (unsigned)n || (unsigned)s >= (unsigned)n) return;
    int pos = atomicAdd(&g_cursor[d], 1);
    g_csr_src[pos]  = s;
    g_csr_attr[pos] = eattr[i];
}
// self-loop fill, loop_attr computed inline (sumattr/max(cnt,1))
__global__ void fill_loop_kernel(int n) {
    int i = blockIdx.x * blockDim.x + threadIdx.x;
    if (i >= n) return;
    int c = g_cnt[i];
    float la = g_sumattr[i] / (float)(c > 1 ? c : 1);
    int pos = atomicAdd(&g_cursor[i], 1);
    g_csr_src[pos]  = i;
    g_csr_attr[pos] = la;
}

// ---------------------------------------------------------------------------
// Weight conversion (all 6 matrices, one launch)
// ---------------------------------------------------------------------------
__global__ void conv_w_all_kernel(const float* __restrict__ Wl1,
                                  const float* __restrict__ Wr1,
                                  const float* __restrict__ Wl2,
                                  const float* __restrict__ Wr2,
                                  const float* __restrict__ Wl3,
                                  const float* __restrict__ Wr3) {
    int i = blockIdx.x * blockDim.x + threadIdx.x;
    int side = i & 1;
    int idx = i >> 1;
    if (idx >= WOFF3 + 256 * 64) return;
    const float* W;
    int K, off;
    if (idx < WOFF2)      { W = side ? Wr1 : Wl1; K = 256; off = idx - WOFF1; }
    else if (idx < WOFF3) { W = side ? Wr2 : Wl2; K = 64;  off = idx - WOFF2; }
    else                  { W = side ? Wr3 : Wl3; K = 64;  off = idx - WOFF3; }
    int nrow = off / K;
    int k = off - nrow * K;
    float v = W[(size_t)k * 256 + nrow];
    __nv_bfloat16 h = __float2bfloat16(v);
    float r = v - __bfloat162float(h);
    g_wh[side][idx] = h;
    g_wl[side][idx] = __float2bfloat16(r);
}

// ---------------------------------------------------------------------------
// HMMA GEMM (mma.sync bf16 3-split) — round-10 proven inner loop (DO NOT
// TOUCH). Loader extended: if Afp != nullptr, read fp32 A and split to
// bf16 hi/lo on the fly (same bytes/elt as bf16 pair; removes conv_a).
// ---------------------------------------------------------------------------
#define KC 64
#define PADW 36
#define ROWB (PADW * 4)
#define SM_AH 0
#define SM_AL (128 * ROWB)
#define SM_BH (2 * 128 * ROWB)
#define SM_BL (3 * 128 * ROWB)
#define GEMM_SMEM (4 * 128 * ROWB)

__device__ __forceinline__ void mma_bf16(float* c, const uint32_t* a,
                                         uint32_t b0, uint32_t b1) {
    asm volatile(
        "mma.sync.aligned.m16n8k16.row.col.f32.bf16.bf16.f32 "
        "{%0,%1,%2,%3}, {%4,%5,%6,%7}, {%8,%9}, {%0,%1,%2,%3};"
        : "+f"(c[0]), "+f"(c[1]), "+f"(c[2]), "+f"(c[3])
        : "r"(a[0]), "r"(a[1]), "r"(a[2]), "r"(a[3]), "r"(b0), "r"(b1));
}

__global__ __launch_bounds__(256)
void gemm_mma_kernel(const __nv_bfloat16* __restrict__ Ah,
                     const __nv_bfloat16* __restrict__ Al,
                     const float* __restrict__ Afp,
                     int woff,
                     const float* __restrict__ bias0, float* __restrict__ C0,
                     const float* __restrict__ bias1, float* __restrict__ C1,
                     int M, int K) {
    extern __shared__ char dsm[];

    const __nv_bfloat16* Bh = g_wh[blockIdx.y] + woff;
    const __nv_bfloat16* Bl = g_wl[blockIdx.y] + woff;
    const float* bias = blockIdx.y ? bias1 : bias0;
    float* C = blockIdx.y ? C1 : C0;
    int m0 = blockIdx.x * 128;
    int n0 = blockIdx.z * 128;

    int tid = threadIdx.x;
    int wid = tid >> 5, lane = tid & 31;
    int warpM = wid & 3, warpN = wid >> 2;
    int r = lane >> 2, q = lane & 3;

    const uint32_t* AHw = (const uint32_t*)(dsm + SM_AH);
    const uint32_t* ALw = (const uint32_t*)(dsm + SM_AL);
    const uint32_t* BHw = (const uint32_t*)(dsm + SM_BH);
    const uint32_t* BLw = (const uint32_t*)(dsm + SM_BL);

    float acc[2][8][4] = {};

    int lrow = tid >> 1;
    int lseg = tid & 1;

    int nchunks = K / KC;
    for (int t = 0; t < nchunks; ++t) {
        int k0 = t * KC;
        {
            int m = m0 + lrow;
            bool v = m < M;
            uint32_t doff = lrow * ROWB + lseg * 64;
            uint4* da_h = (uint4*)(dsm + SM_AH + doff);
            uint4* da_l = (uint4*)(dsm + SM_AL + doff);
            uint4* db_h = (uint4*)(dsm + SM_BH + doff);
            uint4* db_l = (uint4*)(dsm + SM_BL + doff);
            uint4 z = make_uint4(0, 0, 0, 0);
            if (Afp) {
                // fp32 path: 32 floats per thread -> hi/lo bf16 on the fly
                const float4* sa = (const float4*)(Afp + (size_t)m * K + k0 + lseg * 32);
                #pragma unroll
                for (int j = 0; j < 4; ++j) {
                    float4 f0 = v ? sa[2 * j]     : make_float4(0.f, 0.f, 0.f, 0.f);
                    float4 f1 = v ? sa[2 * j + 1] : make_float4(0.f, 0.f, 0.f, 0.f);
                    float fs[8] = {f0.x, f0.y, f0.z, f0.w, f1.x, f1.y, f1.z, f1.w};
                    __nv_bfloat16 hb[8], lb[8];
                    #pragma unroll
                    for (int u = 0; u < 8; ++u) {
                        __nv_bfloat16 h = __float2bfloat16(fs[u]);
                        hb[u] = h;
                        lb[u] = __float2bfloat16(fs[u] - __bfloat162float(h));
                    }
                    da_h[j] = *(const uint4*)hb;
                    da_l[j] = *(const uint4*)lb;
                }
            } else {
                size_t ga = (size_t)m * K + k0 + lseg * 32;
                const uint4* sa_h = (const uint4*)(Ah + ga);
                const uint4* sa_l = (const uint4*)(Al + ga);
                #pragma unroll
                for (int j = 0; j < 4; ++j) {
                    da_h[j] = v ? sa_h[j] : z;
                    da_l[j] = v ? sa_l[j] : z;
                }
            }
            size_t gb = (size_t)(n0 + lrow) * K + k0 + lseg * 32;
            const uint4* sb_h = (const uint4*)(Bh + gb);
            const uint4* sb_l = (const uint4*)(Bl + gb);
            #pragma unroll
            for (int j = 0; j < 4; ++j) {
                db_h[j] = sb_h[j];
                db_l[j] = sb_l[j];
            }
        }
        __syncthreads();

        #pragma unroll
        for (int ks = 0; ks < KC / 16; ++ks) {
            int kw = ks * 8;
            uint32_t ah[2][4], al[2][4];
            #pragma unroll
            for (int mi = 0; mi < 2; ++mi) {
                int rb  = (warpM * 32 + mi * 16 + r) * PADW + kw + q;
                int rb8 = rb + 8 * PADW;
                ah[mi][0] = AHw[rb];     ah[mi][1] = AHw[rb8];
                ah[mi][2] = AHw[rb + 4]; ah[mi][3] = AHw[rb8 + 4];
                al[mi][0] = ALw[rb];     al[mi][1] = ALw[rb8];
                al[mi][2] = ALw[rb + 4]; al[mi][3] = ALw[rb8 + 4];
            }
            #pragma unroll
            for (int ni = 0; ni < 8; ++ni) {
                int nb = (warpN * 64 + ni * 8 + r) * PADW + kw + q;
                uint32_t bh0 = BHw[nb], bh1 = BHw[nb + 4];
                uint32_t bl0 = BLw[nb], bl1 = BLw[nb + 4];
                #pragma unroll
                for (int mi = 0; mi < 2; ++mi) {
                    mma_bf16(acc[mi][ni], ah[mi], bh0, bh1);
                    mma_bf16(acc[mi][ni], ah[mi], bl0, bl1);
                    mma_bf16(acc[mi][ni], al[mi], bh0, bh1);
                }
            }
        }
        __syncthreads();
    }

    #pragma unroll
    for (int ni = 0; ni < 8; ++ni) {
        int gn = n0 + warpN * 64 + ni * 8 + q * 2;
        float bx = bias[gn], by = bias[gn + 1];
        #pragma unroll
        for (int mi = 0; mi < 2; ++mi) {
            int gm = m0 + warpM * 32 + mi * 16 + r;
            if (gm < M) {
                float2 o0 = make_float2(acc[mi][ni][0] + bx, acc[mi][ni][1] + by);
                *(float2*)(C + (size_t)gm * 256 + gn) = o0;
            }
            if (gm + 8 < M) {
                float2 o1 = make_float2(acc[mi][ni][2] + bx, acc[mi][ni][3] + by);
                *(float2*)(C + (size_t)(gm + 8) * 256 + gn) = o1;
            }
        }
    }
}

// ---------------------------------------------------------------------------
// Fused GATv2 edge phase — no-max softmax, x2 unroll (proven round-7 form).
// ---------------------------------------------------------------------------
__global__ void gat_edge_kernel(const float* __restrict__ xl,
                                const float* __restrict__ xr,
                                const float* __restrict__ We,
                                const float* __restrict__ att,
                                const float* __restrict__ bias,
                                const float* __restrict__ prelu_w,
                                float* __restrict__ out,
                                __nv_bfloat16* __restrict__ oh,
                                __nv_bfloat16* __restrict__ ol,
                                int n, int use_prelu) {
    int warp = (blockIdx.x * blockDim.x + threadIdx.x) >> 5;
    if (warp >= n) return;
    int lane = threadIdx.x & 31;
    int sub  = lane & 7;
    int base = (lane >> 3) * CCH + sub * 8;

    float we[8], at[8], xrv[8];
    {
        float4 a = *(const float4*)(We + base);
        float4 b = *(const float4*)(We + base + 4);
        we[0]=a.x; we[1]=a.y; we[2]=a.z; we[3]=a.w;
        we[4]=b.x; we[5]=b.y; we[6]=b.z; we[7]=b.w;
        a = *(const float4*)(att + base);
        b = *(const float4*)(att + base + 4);
        at[0]=a.x; at[1]=a.y; at[2]=a.z; at[3]=a.w;
        at[4]=b.x; at[5]=b.y; at[6]=b.z; at[7]=b.w;
        const float* xp = xr + (size_t)warp * HC + base;
        a = *(const float4*)xp;
        b = *(const float4*)(xp + 4);
        xrv[0]=a.x; xrv[1]=a.y; xrv[2]=a.z; xrv[3]=a.w;
        xrv[4]=b.x; xrv[5]=b.y; xrv[6]=b.z; xrv[7]=b.w;
    }

    int p0 = g_off[warp], p1 = g_off[warp + 1];

    float den = 0.f;
    float acc[8] = {};

    int p = p0;
    for (; p + 1 < p1; p += 2) {
        int s0   = g_csr_src[p];
        int s1   = g_csr_src[p + 1];
        float a0 = g_csr_attr[p];
        float a1 = g_csr_attr[p + 1];
        const float* xp0 = xl + (size_t)s0 * HC + base;
        const float* xp1 = xl + (size_t)s1 * HC + base;
        float4 u0 = *(const float4*)xp0;
        float4 u1 = *(const float4*)(xp0 + 4);
        float4 w0 = *(const float4*)xp1;
        float4 w1 = *(const float4*)(xp1 + 4);
        float xv0[8] = {u0.x, u0.y, u0.z, u0.w, u1.x, u1.y, u1.z, u1.w};
        float xv1[8] = {w0.x, w0.y, w0.z, w0.w, w1.x, w1.y, w1.z, w1.w};
        float sc0 = 0.f, sc1 = 0.f;
        #pragma unroll
        for (int j = 0; j < 8; ++j) {
            float m0_ = xv0[j] + xrv[j] + a0 * we[j];
            float m1_ = xv1[j] + xrv[j] + a1 * we[j];
            m0_ = (m0_ >= 0.f) ? m0_ : NEG_SLOPE * m0_;
            m1_ = (m1_ >= 0.f) ? m1_ : NEG_SLOPE * m1_;
            sc0 += m0_ * at[j];
            sc1 += m1_ * at[j];
        }
        sc0 += __shfl_xor_sync(0xffffffffu, sc0, 1);
        sc1 += __shfl_xor_sync(0xffffffffu, sc1, 1);
        sc0 += __shfl_xor_sync(0xffffffffu, sc0, 2);
        sc1 += __shfl_xor_sync(0xffffffffu, sc1, 2);
        sc0 += __shfl_xor_sync(0xffffffffu, sc0, 4);
        sc1 += __shfl_xor_sync(0xffffffffu, sc1, 4);
        float ex0 = __expf(sc0);
        float ex1 = __expf(sc1);
        den += ex0 + ex1;
        #pragma unroll
        for (int j = 0; j < 8; ++j)
            acc[j] += ex0 * xv0[j] + ex1 * xv1[j];
    }
    if (p < p1) {
        int s   = g_csr_src[p];
        float a = g_csr_attr[p];
        const float* xp = xl + (size_t)s * HC + base;
        float4 v0 = *(const float4*)xp;
        float4 v1 = *(const float4*)(xp + 4);
        float xv[8] = {v0.x, v0.y, v0.z, v0.w, v1.x, v1.y, v1.z, v1.w};
        float sc = 0.f;
        #pragma unroll
        for (int j = 0; j < 8; ++j) {
            float m = xv[j] + xrv[j] + a * we[j];
            m = (m >= 0.f) ? m : NEG_SLOPE * m;
            sc += m * at[j];
        }
        sc += __shfl_xor_sync(0xffffffffu, sc, 1);
        sc += __shfl_xor_sync(0xffffffffu, sc, 2);
        sc += __shfl_xor_sync(0xffffffffu, sc, 4);
        float ex = __expf(sc);
        den += ex;
        #pragma unroll
        for (int j = 0; j < 8; ++j) acc[j] += ex * xv[j];
    }

    float invd = 1.f / (den + 1e-16f);
    float res[8];
    #pragma unroll
    for (int j = 0; j < 8; ++j) {
        float v = acc[j] * invd;
        v += __shfl_xor_sync(0xffffffffu, v, 8);
        v += __shfl_xor_sync(0xffffffffu, v, 16);
        res[j] = v * 0.25f;
    }
    if (lane < 8) {
        if (out) {
            #pragma unroll
            for (int j = 0; j < 8; ++j) {
                int c = sub * 8 + j;
                float o = res[j] + bias[c];
                if (use_prelu) o = (o >= 0.f) ? o : prelu_w[c] * o;
                out[(size_t)warp * CCH + c] = o;
            }
        } else {
            __nv_bfloat16 hbuf[8], lbuf[8];
            #pragma unroll
            for (int j = 0; j < 8; ++j) {
                int c = sub * 8 + j;
                float o = res[j] + bias[c];
                __nv_bfloat16 h = __float2bfloat16(o);
                hbuf[j] = h;
                lbuf[j] = __float2bfloat16(o - __bfloat162float(h));
            }
            *(uint4*)(oh + (size_t)warp * CCH + sub * 8) = *(const uint4*)hbuf;
            *(uint4*)(ol + (size_t)warp * CCH + sub * 8) = *(const uint4*)lbuf;
        }
    }
}

// ---------------------------------------------------------------------------
// Host launch — CSR build on a side stream overlapping conv_w+GEMM1.
// ---------------------------------------------------------------------------
extern "C" void kernel_launch(void* const* d_in, const int* in_sizes, int n_in,
                              void* d_out, int out_size) {
    const float* x     = (const float*)d_in[0];
    const void*  ei    = d_in[1];
    const float* eattr = (const float*)d_in[2];

    const float* Wl[3]   = {(const float*)d_in[3],  (const float*)d_in[10], (const float*)d_in[17]};
    const float* bl[3]   = {(const float*)d_in[4],  (const float*)d_in[11], (const float*)d_in[18]};
    const float* Wr[3]   = {(const float*)d_in[5],  (const float*)d_in[12], (const float*)d_in[19]};
    const float* br[3]   = {(const float*)d_in[6],  (const float*)d_in[13], (const float*)d_in[20]};
    const float* We[3]   = {(const float*)d_in[7],  (const float*)d_in[14], (const float*)d_in[21]};
    const float* att[3]  = {(const float*)d_in[8],  (const float*)d_in[15], (const float*)d_in[22]};
    const float* bias[3] = {(const float*)d_in[9],  (const float*)d_in[16], (const float*)d_in[23]};
    const float* prelu_w = (const float*)d_in[24];

    int n = in_sizes[0] / 256;  // 50000
    int e = in_sizes[2];        // 800000

    float *xl, *xr;
    __nv_bfloat16 *ah, *al;
    cudaGetSymbolAddress((void**)&xl, g_xl);
    cudaGetSymbolAddress((void**)&xr, g_xr);
    cudaGetSymbolAddress((void**)&ah, g_ah);
    cudaGetSymbolAddress((void**)&al, g_al);

    cudaFuncSetAttribute(gemm_mma_kernel,
                         cudaFuncAttributeMaxDynamicSharedMemorySize, GEMM_SMEM);

    static cudaStream_t s_side = nullptr;
    static cudaEvent_t  s_fork = nullptr, s_join = nullptr;
    if (s_side == nullptr) {
        cudaStreamCreateWithFlags(&s_side, cudaStreamNonBlocking);
        cudaEventCreateWithFlags(&s_fork, cudaEventDisableTiming);
        cudaEventCreateWithFlags(&s_join, cudaEventDisableTiming);
    }

    int mtiles = (n + 127) / 128;
    dim3 ggrid(mtiles, 2, 2);
    int edge_blocks = (n * 32 + 255) / 256;
    int scan_blocks = (n + 1023) / 1024;   // 49

    // main: dtype probe (needed by side-stream count)
    detect_kernel<<<1, 32>>>((const int*)ei, e);
    cudaEventRecord(s_fork, 0);
    cudaStreamWaitEvent(s_side, s_fork, 0);

    // side stream: full CSR build (parallel multi-block scan)
    init_kernel<<<(n + 255) / 256, 256, 0, s_side>>>(n);
    count_kernel<<<(e + 255) / 256, 256, 0, s_side>>>(ei, eattr, e, n);
    scan_pass1<<<scan_blocks, 1024, 0, s_side>>>(n);
    scan_pass2<<<1, 64, 0, s_side>>>(scan_blocks, n);
    scan_pass3<<<scan_blocks, 1024, 0, s_side>>>(n);
    fill_kernel<<<(e + 255) / 256, 256, 0, s_side>>>(ei, eattr, e, n);
    fill_loop_kernel<<<(n + 255) / 256, 256, 0, s_side>>>(n);
    cudaEventRecord(s_join, s_side);

    // main stream: weight conversion + layer-1 GEMM (fp32 A path, no conv_a)
    conv_w_all_kernel<<<(2 * (WOFF3 + 256 * 64) + 255) / 256, 256>>>(
        Wl[0], Wr[0], Wl[1], Wr[1], Wl[2], Wr[2]);
    gemm_mma_kernel<<<ggrid, 256, GEMM_SMEM>>>(ah, al, x, WOFF1, bl[0], xl,
                                               br[0], xr, n, 256);

    // join: edge kernel needs GEMM outputs + CSR
    cudaStreamWaitEvent(0, s_join, 0);

    // layer 1 edge -> bf16 split into ah/al
    gat_edge_kernel<<<edge_blocks, 256>>>(xl, xr, We[0], att[0], bias[0],
                                          prelu_w, nullptr, ah, al, n, 0);
    // layer 2
    gemm_mma_kernel<<<ggrid, 256, GEMM_SMEM>>>(ah, al, nullptr, WOFF2, bl[1], xl,
                                               br[1], xr, n, 64);
    gat_edge_kernel<<<edge_blocks, 256>>>(xl, xr, We[1], att[1], bias[1],
                                          prelu_w, nullptr, ah, al, n, 0);
    // layer 3 + PReLU
    gemm_mma_kernel<<<ggrid, 256, GEMM_SMEM>>>(ah, al, nullptr, WOFF3, bl[2], xl,
                                               br[2], xr, n, 64);
    gat_edge_kernel<<<edge_blocks, 256>>>(xl, xr, We[2], att[2], bias[2],
                                          prelu_w, (float*)d_out, nullptr, nullptr, n, 1);
}

// round 15
// speedup vs baseline: 1.0311x; 1.0311x over previous
#include <cuda_runtime.h>
#include <cuda_bf16.h>
#include <math.h>
#include <stdint.h>

// ---------------------------------------------------------------------------
// Problem constants: N=50000, E=800000, IN=256, C=64, H=4
// ---------------------------------------------------------------------------
#define NMAX   50000
#define EMAX   800000
#define E2MAX  (EMAX + NMAX)
#define HC     256          // H*C
#define CCH    64           // C
#define NEG_SLOPE 0.2f
#define SCAN_BLK 64         // >= ceil(NMAX/1024) = 49

// ---------------------------------------------------------------------------
// Scratch (g_cnt / g_sumattr are zero at module load and re-zeroed by
// fill_all_kernel at the end of every invocation -> no init kernel needed)
// ---------------------------------------------------------------------------
__device__ __align__(256) float g_xl[(size_t)NMAX * HC];
__device__ __align__(256) float g_xr[(size_t)NMAX * HC];
__device__ __align__(256) __nv_bfloat16 g_ah[(size_t)NMAX * HC];
__device__ __align__(256) __nv_bfloat16 g_al[(size_t)NMAX * HC];
__device__ __align__(256) __nv_bfloat16 g_wh[2][256 * 256 + 2 * 256 * 64];
__device__ __align__(256) __nv_bfloat16 g_wl[2][256 * 256 + 2 * 256 * 64];
__device__ __align__(256) int   g_cnt[NMAX];
__device__ __align__(256) float g_sumattr[NMAX];
__device__ __align__(256) int   g_off[NMAX + 2];
__device__ __align__(256) int   g_cursor[NMAX];
__device__ __align__(256) int   g_csr_src[E2MAX];
__device__ __align__(256) float g_csr_attr[E2MAX];
__device__ __align__(256) int   g_bsum[SCAN_BLK];
__device__ int g_is64;

#define WOFF1 0
#define WOFF2 (256 * 256)
#define WOFF3 (256 * 256 + 256 * 64)

// ---------------------------------------------------------------------------
// edge_index dtype probe + CSR build
// ---------------------------------------------------------------------------
__device__ __forceinline__ int load_idx(const void* ei, int is64, size_t pos) {
    if (is64) return (int)((const long long*)ei)[pos];
    return ((const int*)ei)[pos];
}
__global__ void detect_kernel(const int* ei32, int e) {
    if (threadIdx.x != 0 || blockIdx.x != 0) return;
    int nz = 0;
    int lim = (e < 64) ? e : 64;
    for (int i = 0; i < lim; ++i) nz |= ei32[2 * i + 1];
    g_is64 = (nz == 0) ? 1 : 0;
}
__global__ void count_kernel(const void* __restrict__ ei,
                             const float* __restrict__ eattr, int e, int n) {
    int i = blockIdx.x * blockDim.x + threadIdx.x;
    if (i >= e) return;
    int is64 = g_is64;
    int d = load_idx(ei, is64, (size_t)e + i);
    if ((unsigned)d >= (unsigned)n) return;
    atomicAdd(&g_cnt[d], 1);
    atomicAdd(&g_sumattr[d], eattr[i]);
}

// --- 2-pass decoupled scan of (cnt[i]+1) ---
// pass 1: per-1024-block sums
__global__ void scan_pass1(int n) {
    __shared__ int wsum[32];
    int tid = threadIdx.x, lane = tid & 31, wid = tid >> 5;
    int i = blockIdx.x * 1024 + tid;
    int x = (i < n) ? (g_cnt[i] + 1) : 0;
    #pragma unroll
    for (int d = 16; d > 0; d >>= 1) x += __shfl_xor_sync(0xffffffffu, x, d);
    if (lane == 0) wsum[wid] = x;
    __syncthreads();
    if (wid == 0) {
        int s = wsum[lane];
        #pragma unroll
        for (int d = 16; d > 0; d >>= 1) s += __shfl_xor_sync(0xffffffffu, s, d);
        if (lane == 0) g_bsum[blockIdx.x] = s;
    }
}
// pass 2 (was pass 3): per-block scan; each block warp-scans the <=64 block
// sums itself to get its offset (removes the separate middle pass).
__global__ void scan_pass3(int n) {
    __shared__ int wsum[32];
    __shared__ int s_incl[64];
    int tid = threadIdx.x, lane = tid & 31, wid = tid >> 5;
    int nb = gridDim.x;

    if (wid == 0) {
        int v0 = (lane < nb) ? g_bsum[lane] : 0;
        int v1 = (lane + 32 < nb) ? g_bsum[lane + 32] : 0;
        int x = v0;
        #pragma unroll
        for (int d = 1; d < 32; d <<= 1) {
            int t = __shfl_up_sync(0xffffffffu, x, d);
            if (lane >= d) x += t;
        }
        int tot0 = __shfl_sync(0xffffffffu, x, 31);
        int y = v1;
        #pragma unroll
        for (int d = 1; d < 32; d <<= 1) {
            int t = __shfl_up_sync(0xffffffffu, y, d);
            if (lane >= d) y += t;
        }
        y += tot0;
        s_incl[lane] = x;
        s_incl[lane + 32] = y;
    }
    __syncthreads();
    int boff = (blockIdx.x > 0) ? s_incl[blockIdx.x - 1] : 0;
    if (blockIdx.x == 0 && tid == 0) g_off[n] = s_incl[nb - 1];

    int i = blockIdx.x * 1024 + tid;
    int v = (i < n) ? (g_cnt[i] + 1) : 0;
    int x = v;
    #pragma unroll
    for (int d = 1; d < 32; d <<= 1) {
        int t = __shfl_up_sync(0xffffffffu, x, d);
        if (lane >= d) x += t;
    }
    if (lane == 31) wsum[wid] = x;
    __syncthreads();
    if (wid == 0) {
        int s = wsum[lane];
        #pragma unroll
        for (int d = 1; d < 32; d <<= 1) {
            int t = __shfl_up_sync(0xffffffffu, s, d);
            if (lane >= d) s += t;
        }
        wsum[lane] = s;
    }
    __syncthreads();
    int woff = (wid > 0) ? wsum[wid - 1] : 0;
    int excl = x - v + woff + boff;
    if (i < n) { g_off[i] = excl; g_cursor[i] = excl; }
}

// fill (edges + self-loops in one launch); also re-zeros cnt/sumattr so the
// next invocation needs no init kernel (deterministic per-call state).
__global__ void fill_all_kernel(const void* __restrict__ ei,
                                const float* __restrict__ eattr, int e, int n) {
    int i = blockIdx.x * blockDim.x + threadIdx.x;
    if (i < e) {
        int is64 = g_is64;
        int s = load_idx(ei, is64, (size_t)i);
        int d = load_idx(ei, is64, (size_t)e + i);
        if ((unsigned)d >= (unsigned)n || (unsigned)s >= (unsigned)n) return;
        int pos = atomicAdd(&g_cursor[d], 1);
        g_csr_src[pos]  = s;
        g_csr_attr[pos] = eattr[i];
    } else if (i < e + n) {
        int j = i - e;
        int c = g_cnt[j];
        float la = g_sumattr[j] / (float)(c > 1 ? c : 1);
        int pos = atomicAdd(&g_cursor[j], 1);
        g_csr_src[pos]  = j;
        g_csr_attr[pos] = la;
        g_cnt[j] = 0;          // reset for next invocation
        g_sumattr[j] = 0.f;
    }
}

// ---------------------------------------------------------------------------
// Weight conversion (all 6 matrices, one launch)
// ---------------------------------------------------------------------------
__global__ void conv_w_all_kernel(const float* __restrict__ Wl1,
                                  const float* __restrict__ Wr1,
                                  const float* __restrict__ Wl2,
                                  const float* __restrict__ Wr2,
                                  const float* __restrict__ Wl3,
                                  const float* __restrict__ Wr3) {
    int i = blockIdx.x * blockDim.x + threadIdx.x;
    int side = i & 1;
    int idx = i >> 1;
    if (idx >= WOFF3 + 256 * 64) return;
    const float* W;
    int K, off;
    if (idx < WOFF2)      { W = side ? Wr1 : Wl1; K = 256; off = idx - WOFF1; }
    else if (idx < WOFF3) { W = side ? Wr2 : Wl2; K = 64;  off = idx - WOFF2; }
    else                  { W = side ? Wr3 : Wl3; K = 64;  off = idx - WOFF3; }
    int nrow = off / K;
    int k = off - nrow * K;
    float v = W[(size_t)k * 256 + nrow];
    __nv_bfloat16 h = __float2bfloat16(v);
    float r = v - __bfloat162float(h);
    g_wh[side][idx] = h;
    g_wl[side][idx] = __float2bfloat16(r);
}

// ---------------------------------------------------------------------------
// HMMA GEMM (mma.sync bf16 3-split) — round-10 proven inner loop (DO NOT
// TOUCH). Loader: Afp != nullptr -> fp32 A split to bf16 hi/lo on the fly.
// ---------------------------------------------------------------------------
#define KC 64
#define PADW 36
#define ROWB (PADW * 4)
#define SM_AH 0
#define SM_AL (128 * ROWB)
#define SM_BH (2 * 128 * ROWB)
#define SM_BL (3 * 128 * ROWB)
#define GEMM_SMEM (4 * 128 * ROWB)

__device__ __forceinline__ void mma_bf16(float* c, const uint32_t* a,
                                         uint32_t b0, uint32_t b1) {
    asm volatile(
        "mma.sync.aligned.m16n8k16.row.col.f32.bf16.bf16.f32 "
        "{%0,%1,%2,%3}, {%4,%5,%6,%7}, {%8,%9}, {%0,%1,%2,%3};"
        : "+f"(c[0]), "+f"(c[1]), "+f"(c[2]), "+f"(c[3])
        : "r"(a[0]), "r"(a[1]), "r"(a[2]), "r"(a[3]), "r"(b0), "r"(b1));
}

__global__ __launch_bounds__(256)
void gemm_mma_kernel(const __nv_bfloat16* __restrict__ Ah,
                     const __nv_bfloat16* __restrict__ Al,
                     const float* __restrict__ Afp,
                     int woff,
                     const float* __restrict__ bias0, float* __restrict__ C0,
                     const float* __restrict__ bias1, float* __restrict__ C1,
                     int M, int K) {
    extern __shared__ char dsm[];

    const __nv_bfloat16* Bh = g_wh[blockIdx.y] + woff;
    const __nv_bfloat16* Bl = g_wl[blockIdx.y] + woff;
    const float* bias = blockIdx.y ? bias1 : bias0;
    float* C = blockIdx.y ? C1 : C0;
    int m0 = blockIdx.x * 128;
    int n0 = blockIdx.z * 128;

    int tid = threadIdx.x;
    int wid = tid >> 5, lane = tid & 31;
    int warpM = wid & 3, warpN = wid >> 2;
    int r = lane >> 2, q = lane & 3;

    const uint32_t* AHw = (const uint32_t*)(dsm + SM_AH);
    const uint32_t* ALw = (const uint32_t*)(dsm + SM_AL);
    const uint32_t* BHw = (const uint32_t*)(dsm + SM_BH);
    const uint32_t* BLw = (const uint32_t*)(dsm + SM_BL);

    float acc[2][8][4] = {};

    int lrow = tid >> 1;
    int lseg = tid & 1;

    int nchunks = K / KC;
    for (int t = 0; t < nchunks; ++t) {
        int k0 = t * KC;
        {
            int m = m0 + lrow;
            bool v = m < M;
            uint32_t doff = lrow * ROWB + lseg * 64;
            uint4* da_h = (uint4*)(dsm + SM_AH + doff);
            uint4* da_l = (uint4*)(dsm + SM_AL + doff);
            uint4* db_h = (uint4*)(dsm + SM_BH + doff);
            uint4* db_l = (uint4*)(dsm + SM_BL + doff);
            uint4 z = make_uint4(0, 0, 0, 0);
            if (Afp) {
                const float4* sa = (const float4*)(Afp + (size_t)m * K + k0 + lseg * 32);
                #pragma unroll
                for (int j = 0; j < 4; ++j) {
                    float4 f0 = v ? sa[2 * j]     : make_float4(0.f, 0.f, 0.f, 0.f);
                    float4 f1 = v ? sa[2 * j + 1] : make_float4(0.f, 0.f, 0.f, 0.f);
                    float fs[8] = {f0.x, f0.y, f0.z, f0.w, f1.x, f1.y, f1.z, f1.w};
                    __nv_bfloat16 hb[8], lb[8];
                    #pragma unroll
                    for (int u = 0; u < 8; ++u) {
                        __nv_bfloat16 h = __float2bfloat16(fs[u]);
                        hb[u] = h;
                        lb[u] = __float2bfloat16(fs[u] - __bfloat162float(h));
                    }
                    da_h[j] = *(const uint4*)hb;
                    da_l[j] = *(const uint4*)lb;
                }
            } else {
                size_t ga = (size_t)m * K + k0 + lseg * 32;
                const uint4* sa_h = (const uint4*)(Ah + ga);
                const uint4* sa_l = (const uint4*)(Al + ga);
                #pragma unroll
                for (int j = 0; j < 4; ++j) {
                    da_h[j] = v ? sa_h[j] : z;
                    da_l[j] = v ? sa_l[j] : z;
                }
            }
            size_t gb = (size_t)(n0 + lrow) * K + k0 + lseg * 32;
            const uint4* sb_h = (const uint4*)(Bh + gb);
            const uint4* sb_l = (const uint4*)(Bl + gb);
            #pragma unroll
            for (int j = 0; j < 4; ++j) {
                db_h[j] = sb_h[j];
                db_l[j] = sb_l[j];
            }
        }
        __syncthreads();

        #pragma unroll
        for (int ks = 0; ks < KC / 16; ++ks) {
            int kw = ks * 8;
            uint32_t ah[2][4], al[2][4];
            #pragma unroll
            for (int mi = 0; mi < 2; ++mi) {
                int rb  = (warpM * 32 + mi * 16 + r) * PADW + kw + q;
                int rb8 = rb + 8 * PADW;
                ah[mi][0] = AHw[rb];     ah[mi][1] = AHw[rb8];
                ah[mi][2] = AHw[rb + 4]; ah[mi][3] = AHw[rb8 + 4];
                al[mi][0] = ALw[rb];     al[mi][1] = ALw[rb8];
                al[mi][2] = ALw[rb + 4]; al[mi][3] = ALw[rb8 + 4];
            }
            #pragma unroll
            for (int ni = 0; ni < 8; ++ni) {
                int nb = (warpN * 64 + ni * 8 + r) * PADW + kw + q;
                uint32_t bh0 = BHw[nb], bh1 = BHw[nb + 4];
                uint32_t bl0 = BLw[nb], bl1 = BLw[nb + 4];
                #pragma unroll
                for (int mi = 0; mi < 2; ++mi) {
                    mma_bf16(acc[mi][ni], ah[mi], bh0, bh1);
                    mma_bf16(acc[mi][ni], ah[mi], bl0, bl1);
                    mma_bf16(acc[mi][ni], al[mi], bh0, bh1);
                }
            }
        }
        __syncthreads();
    }

    #pragma unroll
    for (int ni = 0; ni < 8; ++ni) {
        int gn = n0 + warpN * 64 + ni * 8 + q * 2;
        float bx = bias[gn], by = bias[gn + 1];
        #pragma unroll
        for (int mi = 0; mi < 2; ++mi) {
            int gm = m0 + warpM * 32 + mi * 16 + r;
            if (gm < M) {
                float2 o0 = make_float2(acc[mi][ni][0] + bx, acc[mi][ni][1] + by);
                *(float2*)(C + (size_t)gm * 256 + gn) = o0;
            }
            if (gm + 8 < M) {
                float2 o1 = make_float2(acc[mi][ni][2] + bx, acc[mi][ni][3] + by);
                *(float2*)(C + (size_t)(gm + 8) * 256 + gn) = o1;
            }
        }
    }
}

// ---------------------------------------------------------------------------
// Fused GATv2 edge phase — no-max softmax, x2 unroll (proven round-7 form).
// ---------------------------------------------------------------------------
__global__ void gat_edge_kernel(const float* __restrict__ xl,
                                const float* __restrict__ xr,
                                const float* __restrict__ We,
                                const float* __restrict__ att,
                                const float* __restrict__ bias,
                                const float* __restrict__ prelu_w,
                                float* __restrict__ out,
                                __nv_bfloat16* __restrict__ oh,
                                __nv_bfloat16* __restrict__ ol,
                                int n, int use_prelu) {
    int warp = (blockIdx.x * blockDim.x + threadIdx.x) >> 5;
    if (warp >= n) return;
    int lane = threadIdx.x & 31;
    int sub  = lane & 7;
    int base = (lane >> 3) * CCH + sub * 8;

    float we[8], at[8], xrv[8];
    {
        float4 a = *(const float4*)(We + base);
        float4 b = *(const float4*)(We + base + 4);
        we[0]=a.x; we[1]=a.y; we[2]=a.z; we[3]=a.w;
        we[4]=b.x; we[5]=b.y; we[6]=b.z; we[7]=b.w;
        a = *(const float4*)(att + base);
        b = *(const float4*)(att + base + 4);
        at[0]=a.x; at[1]=a.y; at[2]=a.z; at[3]=a.w;
        at[4]=b.x; at[5]=b.y; at[6]=b.z; at[7]=b.w;
        const float* xp = xr + (size_t)warp * HC + base;
        a = *(const float4*)xp;
        b = *(const float4*)(xp + 4);
        xrv[0]=a.x; xrv[1]=a.y; xrv[2]=a.z; xrv[3]=a.w;
        xrv[4]=b.x; xrv[5]=b.y; xrv[6]=b.z; xrv[7]=b.w;
    }

    int p0 = g_off[warp], p1 = g_off[warp + 1];

    float den = 0.f;
    float acc[8] = {};

    int p = p0;
    for (; p + 1 < p1; p += 2) {
        int s0   = g_csr_src[p];
        int s1   = g_csr_src[p + 1];
        float a0 = g_csr_attr[p];
        float a1 = g_csr_attr[p + 1];
        const float* xp0 = xl + (size_t)s0 * HC + base;
        const float* xp1 = xl + (size_t)s1 * HC + base;
        float4 u0 = *(const float4*)xp0;
        float4 u1 = *(const float4*)(xp0 + 4);
        float4 w0 = *(const float4*)xp1;
        float4 w1 = *(const float4*)(xp1 + 4);
        float xv0[8] = {u0.x, u0.y, u0.z, u0.w, u1.x, u1.y, u1.z, u1.w};
        float xv1[8] = {w0.x, w0.y, w0.z, w0.w, w1.x, w1.y, w1.z, w1.w};
        float sc0 = 0.f, sc1 = 0.f;
        #pragma unroll
        for (int j = 0; j < 8; ++j) {
            float m0_ = xv0[j] + xrv[j] + a0 * we[j];
            float m1_ = xv1[j] + xrv[j] + a1 * we[j];
            m0_ = (m0_ >= 0.f) ? m0_ : NEG_SLOPE * m0_;
            m1_ = (m1_ >= 0.f) ? m1_ : NEG_SLOPE * m1_;
            sc0 += m0_ * at[j];
            sc1 += m1_ * at[j];
        }
        sc0 += __shfl_xor_sync(0xffffffffu, sc0, 1);
        sc1 += __shfl_xor_sync(0xffffffffu, sc1, 1);
        sc0 += __shfl_xor_sync(0xffffffffu, sc0, 2);
        sc1 += __shfl_xor_sync(0xffffffffu, sc1, 2);
        sc0 += __shfl_xor_sync(0xffffffffu, sc0, 4);
        sc1 += __shfl_xor_sync(0xffffffffu, sc1, 4);
        float ex0 = __expf(sc0);
        float ex1 = __expf(sc1);
        den += ex0 + ex1;
        #pragma unroll
        for (int j = 0; j < 8; ++j)
            acc[j] += ex0 * xv0[j] + ex1 * xv1[j];
    }
    if (p < p1) {
        int s   = g_csr_src[p];
        float a = g_csr_attr[p];
        const float* xp = xl + (size_t)s * HC + base;
        float4 v0 = *(const float4*)xp;
        float4 v1 = *(const float4*)(xp + 4);
        float xv[8] = {v0.x, v0.y, v0.z, v0.w, v1.x, v1.y, v1.z, v1.w};
        float sc = 0.f;
        #pragma unroll
        for (int j = 0; j < 8; ++j) {
            float m = xv[j] + xrv[j] + a * we[j];
            m = (m >= 0.f) ? m : NEG_SLOPE * m;
            sc += m * at[j];
        }
        sc += __shfl_xor_sync(0xffffffffu, sc, 1);
        sc += __shfl_xor_sync(0xffffffffu, sc, 2);
        sc += __shfl_xor_sync(0xffffffffu, sc, 4);
        float ex = __expf(sc);
        den += ex;
        #pragma unroll
        for (int j = 0; j < 8; ++j) acc[j] += ex * xv[j];
    }

    float invd = 1.f / (den + 1e-16f);
    float res[8];
    #pragma unroll
    for (int j = 0; j < 8; ++j) {
        float v = acc[j] * invd;
        v += __shfl_xor_sync(0xffffffffu, v, 8);
        v += __shfl_xor_sync(0xffffffffu, v, 16);
        res[j] = v * 0.25f;
    }
    if (lane < 8) {
        if (out) {
            #pragma unroll
            for (int j = 0; j < 8; ++j) {
                int c = sub * 8 + j;
                float o = res[j] + bias[c];
                if (use_prelu) o = (o >= 0.f) ? o : prelu_w[c] * o;
                out[(size_t)warp * CCH + c] = o;
            }
        } else {
            __nv_bfloat16 hbuf[8], lbuf[8];
            #pragma unroll
            for (int j = 0; j < 8; ++j) {
                int c = sub * 8 + j;
                float o = res[j] + bias[c];
                __nv_bfloat16 h = __float2bfloat16(o);
                hbuf[j] = h;
                lbuf[j] = __float2bfloat16(o - __bfloat162float(h));
            }
            *(uint4*)(oh + (size_t)warp * CCH + sub * 8) = *(const uint4*)hbuf;
            *(uint4*)(ol + (size_t)warp * CCH + sub * 8) = *(const uint4*)lbuf;
        }
    }
}

// ---------------------------------------------------------------------------
// Host launch — CSR on side stream; submission order puts gemm1 early for
// ncu sampling: conv_w(1), detect(2), count(3), gemm1(4), p1(5), p3(6),
// fill_all(7), edge1(8)...
// ---------------------------------------------------------------------------
extern "C" void kernel_launch(void* const* d_in, const int* in_sizes, int n_in,
                              void* d_out, int out_size) {
    const float* x     = (const float*)d_in[0];
    const void*  ei    = d_in[1];
    const float* eattr = (const float*)d_in[2];

    const float* Wl[3]   = {(const float*)d_in[3],  (const float*)d_in[10], (const float*)d_in[17]};
    const float* bl[3]   = {(const float*)d_in[4],  (const float*)d_in[11], (const float*)d_in[18]};
    const float* Wr[3]   = {(const float*)d_in[5],  (const float*)d_in[12], (const float*)d_in[19]};
    const float* br[3]   = {(const float*)d_in[6],  (const float*)d_in[13], (const float*)d_in[20]};
    const float* We[3]   = {(const float*)d_in[7],  (const float*)d_in[14], (const float*)d_in[21]};
    const float* att[3]  = {(const float*)d_in[8],  (const float*)d_in[15], (const float*)d_in[22]};
    const float* bias[3] = {(const float*)d_in[9],  (const float*)d_in[16], (const float*)d_in[23]};
    const float* prelu_w = (const float*)d_in[24];

    int n = in_sizes[0] / 256;  // 50000
    int e = in_sizes[2];        // 800000

    float *xl, *xr;
    __nv_bfloat16 *ah, *al;
    cudaGetSymbolAddress((void**)&xl, g_xl);
    cudaGetSymbolAddress((void**)&xr, g_xr);
    cudaGetSymbolAddress((void**)&ah, g_ah);
    cudaGetSymbolAddress((void**)&al, g_al);

    cudaFuncSetAttribute(gemm_mma_kernel,
                         cudaFuncAttributeMaxDynamicSharedMemorySize, GEMM_SMEM);

    static cudaStream_t s_side = nullptr;
    static cudaEvent_t  s_fork = nullptr, s_join = nullptr;
    if (s_side == nullptr) {
        cudaStreamCreateWithFlags(&s_side, cudaStreamNonBlocking);
        cudaEventCreateWithFlags(&s_fork, cudaEventDisableTiming);
        cudaEventCreateWithFlags(&s_join, cudaEventDisableTiming);
    }

    int mtiles = (n + 127) / 128;
    dim3 ggrid(mtiles, 2, 2);
    int edge_blocks = (n * 32 + 255) / 256;
    int scan_blocks = (n + 1023) / 1024;   // 49 (<= SCAN_BLK)

    // 1: weight conversion (main)
    conv_w_all_kernel<<<(2 * (WOFF3 + 256 * 64) + 255) / 256, 256>>>(
        Wl[0], Wr[0], Wl[1], Wr[1], Wl[2], Wr[2]);
    // 2: dtype probe (main), then fork side stream
    detect_kernel<<<1, 32>>>((const int*)ei, e);
    cudaEventRecord(s_fork, 0);
    cudaStreamWaitEvent(s_side, s_fork, 0);
    // 3: CSR count (side)
    count_kernel<<<(e + 255) / 256, 256, 0, s_side>>>(ei, eattr, e, n);
    // 4: layer-1 GEMM (main; fp32 A path, needs only conv_w)
    gemm_mma_kernel<<<ggrid, 256, GEMM_SMEM>>>(ah, al, x, WOFF1, bl[0], xl,
                                               br[0], xr, n, 256);
    // 5-7: scan + fill (side)
    scan_pass1<<<scan_blocks, 1024, 0, s_side>>>(n);
    scan_pass3<<<scan_blocks, 1024, 0, s_side>>>(n);
    fill_all_kernel<<<(e + n + 255) / 256, 256, 0, s_side>>>(ei, eattr, e, n);
    cudaEventRecord(s_join, s_side);

    // join: edge needs GEMM outputs + CSR
    cudaStreamWaitEvent(0, s_join, 0);

    // layer 1 edge -> bf16 split into ah/al
    gat_edge_kernel<<<edge_blocks, 256>>>(xl, xr, We[0], att[0], bias[0],
                                          prelu_w, nullptr, ah, al, n, 0);
    // layer 2
    gemm_mma_kernel<<<ggrid, 256, GEMM_SMEM>>>(ah, al, nullptr, WOFF2, bl[1], xl,
                                               br[1], xr, n, 64);
    gat_edge_kernel<<<edge_blocks, 256>>>(xl, xr, We[1], att[1], bias[1],
                                          prelu_w, nullptr, ah, al, n, 0);
    // layer 3 + PReLU
    gemm_mma_kernel<<<ggrid, 256, GEMM_SMEM>>>(ah, al, nullptr, WOFF3, bl[2], xl,
                                               br[2], xr, n, 64);
    gat_edge_kernel<<<edge_blocks, 256>>>(xl, xr, We[2], att[2], bias[2],
                                          prelu_w, (float*)d_out, nullptr, nullptr, n, 1);
}